// round 16
// baseline (speedup 1.0000x reference)
#include <cuda_runtime.h>
#include <cuda_fp16.h>
#include <math.h>
#include <stdint.h>

// Problem dims
#define BB 4096
#define TT 64
#define FF 256
#define HH 256
#define AA 12
#define MTOT (BB*TT)            // 262144 rows
#define G3  768

// Scratch (device globals; no cudaMalloc allowed)
__device__ __half g_xgh [(size_t)MTOT * G3];   // xg half; reused as t12 [M,512]
__device__ __half g_lath[(size_t)MTOT * HH];   // latent half
__device__ __half g_t1h [(size_t)MTOT * HH];   // features half
__device__ float  g_pa  [(size_t)2 * MTOT * 16];
__device__ float  g_pc  [(size_t)2 * MTOT];
__device__ uint32_t g_wt2h[16 * 7168];         // W_hh frag-major half2 slots
__device__ __half g_wihr[768 * 256];
__device__ __half g_w1c [512 * 256];
__device__ __half g_w2a [256 * 256];
__device__ __half g_w2c [256 * 256];
__device__ float  g_b1c [512];
__device__ float  g_w3f [4096];                // Aw3 tf32 B-fragments (head)

__device__ __forceinline__ float round_tf32(float x) {
    uint32_t r;
    asm("cvt.rna.tf32.f32 %0, %1;" : "=r"(r) : "f"(x));
    return __uint_as_float(r);
}
__device__ __forceinline__ uint32_t cvt_tf32_f(float x) {
    uint32_t r;
    asm("cvt.rna.tf32.f32 %0, %1;" : "=r"(r) : "f"(x));
    return r;
}

__device__ __forceinline__ uint32_t smem_u32(const void* p) {
    uint32_t a;
    asm("{ .reg .u64 t; cvta.to.shared.u64 t, %1; cvt.u32.u64 %0, t; }"
        : "=r"(a) : "l"(p));
    return a;
}

__device__ __forceinline__ void cp16_cg(void* dst, const void* src) {
    asm volatile("cp.async.cg.shared.global [%0], [%1], 16;"
                 :: "r"(smem_u32(dst)), "l"(src) : "memory");
}
__device__ __forceinline__ void l2_prefetch(const void* p) {
    asm volatile("prefetch.global.L2 [%0];" :: "l"(p));
}
#define CP_COMMIT()  asm volatile("cp.async.commit_group;" ::: "memory")
#define CP_WAIT1()   asm volatile("cp.async.wait_group 1;" ::: "memory")
#define CP_WAITALL() asm volatile("cp.async.wait_all;" ::: "memory")

#define LDMX4(r0,r1,r2,r3,addr) \
    asm volatile("ldmatrix.sync.aligned.m8n8.x4.shared.b16 {%0,%1,%2,%3}, [%4];" \
                 : "=r"(r0),"=r"(r1),"=r"(r2),"=r"(r3) : "r"(addr))
#define LDMX2(r0,r1,addr) \
    asm volatile("ldmatrix.sync.aligned.m8n8.x2.shared.b16 {%0,%1}, [%2];" \
                 : "=r"(r0),"=r"(r1) : "r"(addr))

__device__ __forceinline__ void mma_f16(
    float& c0, float& c1, float& c2, float& c3,
    uint32_t a0, uint32_t a1, uint32_t a2, uint32_t a3,
    uint32_t b0, uint32_t b1)
{
    asm volatile(
        "mma.sync.aligned.m16n8k16.row.col.f32.f16.f16.f32 "
        "{%0,%1,%2,%3}, {%4,%5,%6,%7}, {%8,%9}, {%0,%1,%2,%3};"
        : "+f"(c0), "+f"(c1), "+f"(c2), "+f"(c3)
        : "r"(a0), "r"(a1), "r"(a2), "r"(a3), "r"(b0), "r"(b1));
}
__device__ __forceinline__ void mma_tf32(
    float& c0, float& c1, float& c2, float& c3,
    uint32_t a0, uint32_t a1, uint32_t a2, uint32_t a3,
    uint32_t b0, uint32_t b1)
{
    asm volatile(
        "mma.sync.aligned.m16n8k8.row.col.f32.tf32.tf32.f32 "
        "{%0,%1,%2,%3}, {%4,%5,%6,%7}, {%8,%9}, {%0,%1,%2,%3};"
        : "+f"(c0), "+f"(c1), "+f"(c2), "+f"(c3)
        : "r"(a0), "r"(a1), "r"(a2), "r"(a3), "r"(b0), "r"(b1));
}

__device__ __forceinline__ uint32_t pack_h2(float a, float b) {
    __half2 h = __floats2half2_rn(a, b);
    return *(uint32_t*)&h;
}

// ===========================================================================
// Prep: all weights -> half (+ W_hh fragment-major half2 slots + Aw3 frags)
// ===========================================================================
#define PREP_F4  114688
#define PREP_WHH (PREP_F4 + 98304)            // 212992
#define PREP_TOT (PREP_WHH + 4096)            // 217088 -> 848 blocks
__global__ void prep_all(
    const float4* __restrict__ Wih, const float4* __restrict__ Aw1,
    const float4* __restrict__ Cw1, const float4* __restrict__ Aw2,
    const float4* __restrict__ Cw2, const float* __restrict__ Ab1,
    const float* __restrict__ Cb1, const float*  __restrict__ W_hh,
    const float*  __restrict__ Aw3,
    uint2* __restrict__ wihr, uint2* __restrict__ w1c,
    uint2* __restrict__ w2a, uint2* __restrict__ w2c,
    float* __restrict__ b1c, uint32_t* __restrict__ Wt2h,
    float* __restrict__ w3f)
{
    int i = blockIdx.x * 256 + threadIdx.x;
    if (i < PREP_F4) {
        const float4* src;
        uint2* dst;
        if (i < 49152)      { src = Wih + i;            dst = wihr + i; }
        else if (i < 65536) { src = Aw1 + (i - 49152);  dst = w1c + (i - 49152); }
        else if (i < 81920) { src = Cw1 + (i - 65536);  dst = w1c + 16384 + (i - 65536); }
        else if (i < 98304) { src = Aw2 + (i - 81920);  dst = w2a + (i - 81920); }
        else                { src = Cw2 + (i - 98304);  dst = w2c + (i - 98304); }
        float4 v = *src;
        *dst = make_uint2(pack_h2(v.x, v.y), pack_h2(v.z, v.w));
        if (i < 256)       b1c[i] = Ab1[i];
        else if (i < 512)  b1c[i] = Cb1[i - 256];
    } else if (i < PREP_WHH) {
        int j2 = i - PREP_F4;              // 0..98303
        int kt  = j2 / 6144;
        int rem = j2 % 6144;
        int s   = rem / 24;                // slot = wn*32+lane
        int idx = rem % 24;
        int wn = s >> 5, lane = s & 31;
        int j12 = idx >> 1, b = idx & 1;
        int g = j12 >> 2, nt = j12 & 3;
        int col = g * 256 + wn * 32 + nt * 8 + (lane >> 2);
        int k0  = kt * 16 + 2 * (lane & 3) + 8 * b;
        Wt2h[kt * 7168 + s * 28 + idx] =
            pack_h2(W_hh[(size_t)col * 256 + k0], W_hh[(size_t)col * 256 + k0 + 1]);
    } else if (i < PREP_TOT) {
        int j3 = i - PREP_WHH;             // 0..4095
        int ksubg = j3 >> 7;
        int rest  = j3 & 127;
        int ntile = rest >> 6;
        int lane  = (rest >> 1) & 31;
        int r     = rest & 1;
        int kg = ksubg * 8 + (lane & 3) + 4 * r;
        int a  = ntile * 8 + (lane >> 2);
        w3f[j3] = (a < AA) ? round_tf32(Aw3[a * 256 + kg]) : 0.f;
    }
}

// features fp32 -> half
__global__ void feat_half(const float4* __restrict__ src, uint2* __restrict__ dst)
{
    size_t i = (size_t)blockIdx.x * 256 + threadIdx.x;
    float4 v = src[i];
    dst[i] = make_uint2(pack_h2(v.x, v.y), pack_h2(v.z, v.w));
}

// ===========================================================================
// fp16 mma GEMM: tile 128x128, BK=64 (4 x k16 steps/stage), 2-stage cp.async,
// 2 CTAs/SM, ldmatrix fragments, per-CTA k-tile rotation.
// ===========================================================================
#define GBM 128
#define GBN 128
#define GBK 64
#define PH 72                                  // halves pitch (144B rows)
#define ASTG (GBM * PH)                        // 9216 halves per A/B stage
#define GEMM_SMEM (4 * ASTG * 2 + GBN * 4)     // 73728 + 512 = 74240 B

__device__ __forceinline__ void gemm16_mainloop(
    __half* smh, const __half* Ag, const __half* Wg,
    int K, int a_lm, int b_lm, float acc[4][4][4],
    int lrow, int lkq, int phase)
{
    const uint32_t sbase = smem_u32(smh);
    const int NK = K / GBK;                    // 4 for K=256
    auto stage_copy = [&](int kt) {
        int tl = kt + phase;
        if (tl >= NK) tl -= NK;
        __half* st = smh + (kt & 1) * 2 * ASTG;
        const __half* ap = Ag + tl * GBK;
        const __half* wp = Wg + tl * GBK;
        __half* dA = st + lrow * PH + lkq;
        __half* dB = st + ASTG + lrow * PH + lkq;
#pragma unroll
        for (int u = 0; u < 4; u++) {
            cp16_cg(dA + 8 * u, ap + 8 * u);
            cp16_cg(dB + 8 * u, wp + 8 * u);
        }
    };
    stage_copy(0); CP_COMMIT();
    stage_copy(1); CP_COMMIT();
    for (int kt = 0; kt < NK; kt++) {
        if (kt < NK - 1) { CP_WAIT1(); } else { CP_WAITALL(); }
        __syncthreads();
        const uint32_t bufA = sbase + ((kt & 1) * 2 * ASTG) * 2;
        const uint32_t bufB = bufA + ASTG * 2;
#pragma unroll
        for (int ks = 0; ks < 4; ks++) {
            const int k0 = ks * 16;
            uint32_t a[4][4];
#pragma unroll
            for (int mt = 0; mt < 4; mt++)
                LDMX4(a[mt][0], a[mt][1], a[mt][2], a[mt][3],
                      bufA + (a_lm + mt * 16 * PH + k0) * 2);
            uint32_t b[4][2];
#pragma unroll
            for (int nt = 0; nt < 4; nt++)
                LDMX2(b[nt][0], b[nt][1],
                      bufB + (b_lm + nt * 8 * PH + k0) * 2);
#pragma unroll
            for (int mt = 0; mt < 4; mt++)
#pragma unroll
                for (int nt = 0; nt < 4; nt++)
                    mma_f16(acc[mt][nt][0], acc[mt][nt][1],
                            acc[mt][nt][2], acc[mt][nt][3],
                            a[mt][0], a[mt][1], a[mt][2], a[mt][3],
                            b[nt][0], b[nt][1]);
        }
        __syncthreads();
        if (kt + 2 < NK) { stage_copy(kt + 2); CP_COMMIT(); }
    }
}

template<bool DO_TANH>
__global__ __launch_bounds__(256, 2) void gemm_h(
    const __half* __restrict__ A, const __half* __restrict__ W,
    const float* __restrict__ bias, __half* __restrict__ C,
    int N, int K, int lda)
{
    extern __shared__ __half smh[];
    float* sBias = (float*)(smh + 4 * ASTG);
    const int tid  = threadIdx.x;
    const int lane = tid & 31;
    const int wid  = tid >> 5;
    const int wm   = wid >> 2;
    const int wn   = wid & 3;
    const int    bn = blockIdx.x * GBN;
    const size_t bm = (size_t)blockIdx.y * GBM;
    if (tid < GBN) sBias[tid] = bias[bn + tid];
    const int lrow = tid >> 1;
    const int lkq  = (tid & 1) * 32;
    const __half* Ag = A + (bm + lrow) * lda + lkq;
    const __half* Wg = W + ((size_t)(bn + lrow)) * K + lkq;
    const int a_lm = (wm * 64 + (lane & 15)) * PH + ((lane >> 4) << 3);
    const int b_lm = (wn * 32 + (lane & 7)) * PH + (((lane >> 3) & 1) << 3);
    const int phase = blockIdx.y & ((K / GBK) - 1);

    float acc[4][4][4];
#pragma unroll
    for (int mt = 0; mt < 4; mt++)
#pragma unroll
        for (int nt = 0; nt < 4; nt++)
#pragma unroll
            for (int q = 0; q < 4; q++) acc[mt][nt][q] = 0.f;

    gemm16_mainloop(smh, Ag, Wg, K, a_lm, b_lm, acc, lrow, lkq, phase);

#pragma unroll
    for (int mt = 0; mt < 4; mt++) {
        const size_t row = bm + wm * 64 + mt * 16 + (lane >> 2);
        __half* c0p = C + row * N + bn + wn * 32;
        __half* c1p = c0p + (size_t)8 * N;
#pragma unroll
        for (int nt = 0; nt < 4; nt++) {
            const int cc = nt * 8 + (lane & 3) * 2;
            const float bx = sBias[wn * 32 + cc];
            const float by = sBias[wn * 32 + cc + 1];
            float v0 = acc[mt][nt][0] + bx, v1 = acc[mt][nt][1] + by;
            float v2 = acc[mt][nt][2] + bx, v3 = acc[mt][nt][3] + by;
            if (DO_TANH) {
                v0 = tanhf(v0); v1 = tanhf(v1);
                v2 = tanhf(v2); v3 = tanhf(v3);
            }
            *(uint32_t*)(c0p + cc) = pack_h2(v0, v1);
            *(uint32_t*)(c1p + cc) = pack_h2(v2, v3);
        }
    }
}

// ===========================================================================
// Layer-2 GEMM (fp16 mainloop, BK=64) fused with heads -> partials.
// ===========================================================================
template<bool ACTOR>
__global__ __launch_bounds__(256, 2) void gemm_l2(
    const __half* __restrict__ A, const __half* __restrict__ W,
    const float* __restrict__ bias, const float* __restrict__ w3f,
    const float* __restrict__ Cw3,
    float* __restrict__ partial, int K, int lda)
{
    extern __shared__ __half smh[];
    float* sBias = (float*)(smh + 4 * ASTG);
    float* sred  = (float*)smh;             // reuse stage area post-mainloop
    const int tid  = threadIdx.x;
    const int lane = tid & 31;
    const int wid  = tid >> 5;
    const int wm   = wid >> 2;
    const int wn   = wid & 3;
    const int    bn = blockIdx.x * GBN;
    const size_t bm = (size_t)blockIdx.y * GBM;
    if (tid < GBN) sBias[tid] = bias[bn + tid];
    const int lrow = tid >> 1;
    const int lkq  = (tid & 1) * 32;
    const __half* Ag = A + (bm + lrow) * lda + lkq;
    const __half* Wg = W + ((size_t)(bn + lrow)) * K + lkq;
    const int a_lm = (wm * 64 + (lane & 15)) * PH + ((lane >> 4) << 3);
    const int b_lm = (wn * 32 + (lane & 7)) * PH + (((lane >> 3) & 1) << 3);
    const int phase = blockIdx.y & ((K / GBK) - 1);

    float acc[4][4][4];
#pragma unroll
    for (int mt = 0; mt < 4; mt++)
#pragma unroll
        for (int nt = 0; nt < 4; nt++)
#pragma unroll
            for (int q = 0; q < 4; q++) acc[mt][nt][q] = 0.f;

    gemm16_mainloop(smh, Ag, Wg, K, a_lm, b_lm, acc, lrow, lkq, phase);

#pragma unroll
    for (int mt = 0; mt < 4; mt++)
#pragma unroll
        for (int nt = 0; nt < 4; nt++) {
            const int cc = nt * 8 + (lane & 3) * 2;
            const float bx = sBias[wn * 32 + cc];
            const float by = sBias[wn * 32 + cc + 1];
            acc[mt][nt][0] = tanhf(acc[mt][nt][0] + bx);
            acc[mt][nt][1] = tanhf(acc[mt][nt][1] + by);
            acc[mt][nt][2] = tanhf(acc[mt][nt][2] + bx);
            acc[mt][nt][3] = tanhf(acc[mt][nt][3] + by);
        }

    const int j    = lane & 3;
    const int srcA = (lane & ~3) | (j >> 1);
    const int srcB = (lane & ~3) | (2 + (j >> 1));
    const bool odd = (lane & 1);

    if (ACTOR) {
        float hacc[4][2][4];
#pragma unroll
        for (int mt = 0; mt < 4; mt++)
#pragma unroll
            for (int n2 = 0; n2 < 2; n2++)
#pragma unroll
                for (int q = 0; q < 4; q++) hacc[mt][n2][q] = 0.f;

        const int ksgbase = (bn >> 3) + wn * 4;
#pragma unroll
        for (int ks = 0; ks < 4; ks++) {
            float2 bf0 = *(const float2*)(w3f + (((ksgbase + ks) * 2 + 0) * 32 + lane) * 2);
            float2 bf1 = *(const float2*)(w3f + (((ksgbase + ks) * 2 + 1) * 32 + lane) * 2);
            uint32_t b00 = __float_as_uint(bf0.x), b01 = __float_as_uint(bf0.y);
            uint32_t b10 = __float_as_uint(bf1.x), b11 = __float_as_uint(bf1.y);
#pragma unroll
            for (int mt = 0; mt < 4; mt++) {
                float c0 = acc[mt][ks][0], c1 = acc[mt][ks][1];
                float c2 = acc[mt][ks][2], c3 = acc[mt][ks][3];
                float t0 = __shfl_sync(0xffffffffu, c0, srcA);
                float t1 = __shfl_sync(0xffffffffu, c1, srcA);
                float t2 = __shfl_sync(0xffffffffu, c2, srcA);
                float t3 = __shfl_sync(0xffffffffu, c3, srcA);
                float u0 = __shfl_sync(0xffffffffu, c0, srcB);
                float u1 = __shfl_sync(0xffffffffu, c1, srcB);
                float u2 = __shfl_sync(0xffffffffu, c2, srcB);
                float u3 = __shfl_sync(0xffffffffu, c3, srcB);
                uint32_t a0 = cvt_tf32_f(odd ? t1 : t0);
                uint32_t a1 = cvt_tf32_f(odd ? t3 : t2);
                uint32_t a2 = cvt_tf32_f(odd ? u1 : u0);
                uint32_t a3 = cvt_tf32_f(odd ? u3 : u2);
                mma_tf32(hacc[mt][0][0], hacc[mt][0][1], hacc[mt][0][2], hacc[mt][0][3],
                         a0, a1, a2, a3, b00, b01);
                mma_tf32(hacc[mt][1][0], hacc[mt][1][1], hacc[mt][1][2], hacc[mt][1][3],
                         a0, a1, a2, a3, b10, b11);
            }
        }
        for (int rr = 0; rr < 4; rr++) {
            if (wn == rr) {
#pragma unroll
                for (int mt = 0; mt < 4; mt++)
#pragma unroll
                    for (int n2 = 0; n2 < 2; n2++)
#pragma unroll
                        for (int q = 0; q < 4; q++) {
                            int row = wm * 64 + mt * 16 + (lane >> 2) + 8 * (q >> 1);
                            int col = n2 * 8 + 2 * (lane & 3) + (q & 1);
                            if (rr == 0) sred[row * 17 + col] = hacc[mt][n2][q];
                            else         sred[row * 17 + col] += hacc[mt][n2][q];
                        }
            }
            __syncthreads();
        }
        const size_t pbase = (size_t)blockIdx.x * MTOT * 16 + bm * 16;
        for (int i = tid; i < 128 * 16; i += 256)
            partial[pbase + i] = sred[(i >> 4) * 17 + (i & 15)];
    } else {
        float2 cw[4];
#pragma unroll
        for (int nt = 0; nt < 4; nt++)
            cw[nt] = *(const float2*)(Cw3 + bn + wn * 32 + nt * 8 + 2 * (lane & 3));
        float rsum[4][2];
#pragma unroll
        for (int mt = 0; mt < 4; mt++) {
            float s0 = 0.f, s1 = 0.f;
#pragma unroll
            for (int nt = 0; nt < 4; nt++) {
                s0 = fmaf(acc[mt][nt][0], cw[nt].x, s0);
                s0 = fmaf(acc[mt][nt][1], cw[nt].y, s0);
                s1 = fmaf(acc[mt][nt][2], cw[nt].x, s1);
                s1 = fmaf(acc[mt][nt][3], cw[nt].y, s1);
            }
            s0 += __shfl_xor_sync(0xffffffffu, s0, 1);
            s0 += __shfl_xor_sync(0xffffffffu, s0, 2);
            s1 += __shfl_xor_sync(0xffffffffu, s1, 1);
            s1 += __shfl_xor_sync(0xffffffffu, s1, 2);
            rsum[mt][0] = s0; rsum[mt][1] = s1;
        }
        for (int rr = 0; rr < 4; rr++) {
            if (wn == rr && (lane & 3) == 0) {
#pragma unroll
                for (int mt = 0; mt < 4; mt++)
#pragma unroll
                    for (int qh = 0; qh < 2; qh++) {
                        int row = wm * 64 + mt * 16 + (lane >> 2) + 8 * qh;
                        if (rr == 0) sred[row] = rsum[mt][qh];
                        else         sred[row] += rsum[mt][qh];
                    }
            }
            __syncthreads();
        }
        const size_t pbase = (size_t)blockIdx.x * MTOT + bm;
        if (tid < 128) partial[pbase + tid] = sred[tid];
    }
}

// combine partials -> out[:,0:13]
__global__ __launch_bounds__(256) void combine_kernel(
    const float* __restrict__ pa, const float* __restrict__ pc,
    const float* __restrict__ Ab3, const float* __restrict__ Cb3,
    float* __restrict__ out)
{
    size_t m = (size_t)blockIdx.x * 256 + threadIdx.x;
    const float* p0 = pa + m * 16;
    const float* p1 = pa + (size_t)MTOT * 16 + m * 16;
    float* o = out + m * 13;
#pragma unroll
    for (int a = 0; a < 12; a++)
        o[a] = p0[a] + p1[a] + Ab3[a];
    o[12] = pc[m] + pc[MTOT + m] + Cb3[0];
}

// ===========================================================================
// GRU scan fp16 (unchanged from R15)
// ===========================================================================
#define RB2 32
#define HT_PH 264
#define WS_U32 7168
#define GRU_SMEM (3*WS_U32*4 + 32*HT_PH*2 + 32*64*4 + 768*4)   // 114176 B

__global__ __launch_bounds__(512, 1) void gru_mma(
    const __half* __restrict__ xgh, const float* __restrict__ h0,
    const uint32_t* __restrict__ Wt2h, const float* __restrict__ b_hh,
    const int* __restrict__ starts,
    __half* __restrict__ lath, float* __restrict__ h_out)
{
    extern __shared__ char smraw[];
    uint32_t* ws  = (uint32_t*)smraw;
    __half*   hth = (__half*)(ws + 3 * WS_U32);
    int*      sst = (int*)(hth + 32 * HT_PH);
    float*    sbh = (float*)(sst + 32 * 64);

    const int tid  = threadIdx.x;
    const int lane = tid & 31;
    const int w    = tid >> 5;
    const int wm   = w >> 3;
    const int wn   = w & 7;
    const int b0   = blockIdx.x * RB2;
    const int phase = blockIdx.x & 15;

    for (int i = tid; i < 32 * 64; i += 512)
        sst[i] = starts[(size_t)(b0 + (i >> 6)) * TT + (i & 63)];
    for (int i = tid; i < 768; i += 512) sbh[i] = b_hh[i];

    float2 hreg[2][4];
#pragma unroll
    for (int rh = 0; rh < 2; rh++) {
        const int row = wm * 16 + rh * 8 + (lane >> 2);
        const float m0 = starts[(size_t)(b0 + row) * TT] ? 0.f : 1.f;
#pragma unroll
        for (int nt = 0; nt < 4; nt++) {
            const int c = wn * 32 + nt * 8 + (lane & 3) * 2;
            float2 v = *(const float2*)(h0 + (size_t)(b0 + row) * 256 + c);
            v.x *= m0; v.y *= m0;
            hreg[rh][nt] = v;
            *(uint32_t*)(hth + row * HT_PH + c) = pack_h2(v.x, v.y);
        }
    }

    auto stageW = [&](int tile, int buf) {
        const float4* src = (const float4*)(Wt2h + (size_t)tile * WS_U32);
        float4* dst = (float4*)(ws + buf * WS_U32);
        cp16_cg(dst + tid,        src + tid);
        cp16_cg(dst + 512 + tid,  src + 512 + tid);
        cp16_cg(dst + 1024 + tid, src + 1024 + tid);
        if (tid < 256) cp16_cg(dst + 1536 + tid, src + 1536 + tid);
    };

    stageW(phase, 0); CP_COMMIT();
    stageW((phase + 1) & 15, 1); CP_COMMIT();

    const uint32_t ht_lm = smem_u32(hth)
        + ((wm * 16 + (lane & 15)) * HT_PH + ((lane >> 4) << 3)) * 2;
    const int bslot = (wn * 32 + lane) * 28;

    const int KS_TOTAL = TT * 16;
    int ks = 0;

    for (int t = 0; t < TT; t++) {
        float acc[12][4];
#pragma unroll
        for (int j = 0; j < 12; j++)
#pragma unroll
            for (int q = 0; q < 4; q++) acc[j][q] = 0.f;

        for (int kt = 0; kt < 16; kt++) {
            if (ks < KS_TOTAL - 1) { CP_WAIT1(); } else { CP_WAITALL(); }
            __syncthreads();

            if (ks + 2 < KS_TOTAL) {
                stageW((phase + ks + 2) & 15, (ks + 2) % 3);
                CP_COMMIT();
            }

            if (tid < 24) {
                int li = kt * 24 + tid;
                int r = li / 12, cl = li % 12;
                l2_prefetch((const char*)(xgh + ((size_t)(b0 + r) * TT + t) * G3)
                            + cl * 128);
            }

            const int tc = (phase + ks) & 15;
            const uint32_t* wb = ws + (ks % 3) * WS_U32 + bslot;
            uint32_t a0, a1, a2, a3;
            LDMX4(a0, a1, a2, a3, ht_lm + tc * 32);
            float4 bf[6];
#pragma unroll
            for (int u = 0; u < 6; u++)
                bf[u] = *(const float4*)(wb + u * 4);
            const uint32_t* bw = (const uint32_t*)bf;
#pragma unroll
            for (int j = 0; j < 12; j++)
                mma_f16(acc[j][0], acc[j][1], acc[j][2], acc[j][3],
                        a0, a1, a2, a3, bw[j * 2], bw[j * 2 + 1]);
            ks++;
        }
        __syncthreads();

#pragma unroll
        for (int rh = 0; rh < 2; rh++) {
            const int row  = wm * 16 + rh * 8 + (lane >> 2);
            const int grow = b0 + row;
            const size_t gbt = (size_t)grow * TT + t;
            const __half* xb = xgh + gbt * G3;
            __half* lb = lath + gbt * 256;
            float msk = 1.f;
            if (t < TT - 1) msk = sst[row * 64 + t + 1] ? 0.f : 1.f;
            const int q = rh * 2;
#pragma unroll
            for (int nt = 0; nt < 4; nt++) {
                const int c = wn * 32 + nt * 8 + (lane & 3) * 2;
                float2 xr = __half22float2(*(const __half2*)(xb + c));
                float2 xz = __half22float2(*(const __half2*)(xb + 256 + c));
                float2 xn = __half22float2(*(const __half2*)(xb + 512 + c));
                float hr0 = acc[nt][q]         + sbh[c];
                float hr1 = acc[nt][q + 1]     + sbh[c + 1];
                float hz0 = acc[4 + nt][q]     + sbh[256 + c];
                float hz1 = acc[4 + nt][q + 1] + sbh[256 + c + 1];
                float hn0 = acc[8 + nt][q]     + sbh[512 + c];
                float hn1 = acc[8 + nt][q + 1] + sbh[512 + c + 1];
                float r0 = 1.f / (1.f + __expf(-(xr.x + hr0)));
                float r1 = 1.f / (1.f + __expf(-(xr.y + hr1)));
                float z0 = 1.f / (1.f + __expf(-(xz.x + hz0)));
                float z1 = 1.f / (1.f + __expf(-(xz.y + hz1)));
                float n0 = tanhf(xn.x + r0 * hn0);
                float n1 = tanhf(xn.y + r1 * hn1);
                float v0 = (1.f - z0) * n0 + z0 * hreg[rh][nt].x;
                float v1 = (1.f - z1) * n1 + z1 * hreg[rh][nt].y;
                *(uint32_t*)(lb + c) = pack_h2(v0, v1);
                if (t == TT - 1) {
                    *(float2*)(h_out + (size_t)grow * 256 + c) = make_float2(v0, v1);
                } else {
                    float m0 = v0 * msk, m1 = v1 * msk;
                    hreg[rh][nt] = make_float2(m0, m1);
                    *(uint32_t*)(hth + row * HT_PH + c) = pack_h2(m0, m1);
                }
            }
        }
    }
}

__global__ void std_kernel(const float* __restrict__ log_std, float* __restrict__ out)
{
    int a = threadIdx.x;
    if (a < AA) {
        float v = log_std[a];
        v = fminf(fmaxf(v, -2.0f), -0.5f);
        out[a] = __expf(v);
    }
}

// ---------------------------------------------------------------------------
extern "C" void kernel_launch(void* const* d_in, const int* in_sizes, int n_in,
                              void* d_out, int out_size)
{
    const float* features = (const float*)d_in[0];
    const float* hidden   = (const float*)d_in[1];
    const float* W_ih     = (const float*)d_in[2];
    const float* W_hh     = (const float*)d_in[3];
    const float* b_ih     = (const float*)d_in[4];
    const float* b_hh     = (const float*)d_in[5];
    const float* Aw1      = (const float*)d_in[6];
    const float* Ab1      = (const float*)d_in[7];
    const float* Aw2      = (const float*)d_in[8];
    const float* Ab2      = (const float*)d_in[9];
    const float* Aw3      = (const float*)d_in[10];
    const float* Ab3      = (const float*)d_in[11];
    const float* Cw1      = (const float*)d_in[12];
    const float* Cb1      = (const float*)d_in[13];
    const float* Cw2      = (const float*)d_in[14];
    const float* Cb2      = (const float*)d_in[15];
    const float* Cw3      = (const float*)d_in[16];
    const float* Cb3      = (const float*)d_in[17];
    const float* log_std  = (const float*)d_in[18];
    const int*   starts   = (const int*)d_in[19];

    float* out      = (float*)d_out;
    float* out_main = out;
    float* out_std  = out + (size_t)MTOT * 13;
    float* out_h    = out + (size_t)MTOT * 13 + AA;

    __half *xgh, *lath, *t1h, *wihr, *w1c, *w2a, *w2c;
    float *pa, *pc, *b1c, *w3f;
    uint32_t *wt2h;
    cudaGetSymbolAddress((void**)&xgh,  g_xgh);
    cudaGetSymbolAddress((void**)&lath, g_lath);
    cudaGetSymbolAddress((void**)&t1h,  g_t1h);
    cudaGetSymbolAddress((void**)&pa,   g_pa);
    cudaGetSymbolAddress((void**)&pc,   g_pc);
    cudaGetSymbolAddress((void**)&wt2h, g_wt2h);
    cudaGetSymbolAddress((void**)&wihr, g_wihr);
    cudaGetSymbolAddress((void**)&w1c,  g_w1c);
    cudaGetSymbolAddress((void**)&w2a,  g_w2a);
    cudaGetSymbolAddress((void**)&w2c,  g_w2c);
    cudaGetSymbolAddress((void**)&b1c,  g_b1c);
    cudaGetSymbolAddress((void**)&w3f,  g_w3f);

    cudaFuncSetAttribute(gemm_h<false>,
                         cudaFuncAttributeMaxDynamicSharedMemorySize, GEMM_SMEM);
    cudaFuncSetAttribute(gemm_h<true>,
                         cudaFuncAttributeMaxDynamicSharedMemorySize, GEMM_SMEM);
    cudaFuncSetAttribute(gemm_l2<true>,
                         cudaFuncAttributeMaxDynamicSharedMemorySize, GEMM_SMEM);
    cudaFuncSetAttribute(gemm_l2<false>,
                         cudaFuncAttributeMaxDynamicSharedMemorySize, GEMM_SMEM);
    cudaFuncSetAttribute(gru_mma,
                         cudaFuncAttributeMaxDynamicSharedMemorySize, GRU_SMEM);

    dim3 blk(256);

    // 1) weight prep
    prep_all<<<PREP_TOT/256, blk>>>(
        (const float4*)W_ih, (const float4*)Aw1, (const float4*)Cw1,
        (const float4*)Aw2, (const float4*)Cw2, Ab1, Cb1, W_hh, Aw3,
        (uint2*)wihr, (uint2*)w1c, (uint2*)w2a, (uint2*)w2c,
        b1c, wt2h, w3f);
    // 2) features -> half
    feat_half<<<((size_t)MTOT*256)/1024, blk>>>(
        (const float4*)features, (uint2*)t1h);
    // 3) std (independent)
    std_kernel<<<1, 32>>>(log_std, out_std);
    // 4) xg = features @ W_ih^T + b_ih (half out)   <-- profiled launch
    gemm_h<false><<<dim3(G3/GBN, MTOT/GBM), blk, GEMM_SMEM>>>(
        t1h, wihr, b_ih, xgh, G3, FF, FF);
    // 5) GRU scan -> lat (half), h_last (fp32)
    gru_mma<<<BB/RB2, dim3(512), GRU_SMEM>>>(
        xgh, hidden, wt2h, b_hh, starts, lath, out_h);
    // 6) fused actor+critic layer1 (reuses g_xgh as [M,512] half)
    gemm_h<true><<<dim3(512/GBN, MTOT/GBM), blk, GEMM_SMEM>>>(
        lath, w1c, b1c, xgh, 512, HH, HH);
    // 7,8) layer2 + fused heads -> partials
    gemm_l2<true><<<dim3(HH/GBN, MTOT/GBM), blk, GEMM_SMEM>>>(
        xgh,       w2a, Ab2, w3f, Cw3, pa, HH, 512);
    gemm_l2<false><<<dim3(HH/GBN, MTOT/GBM), blk, GEMM_SMEM>>>(
        xgh + 256, w2c, Cb2, w3f, Cw3, pc, HH, 512);
    // 9) combine partials + biases -> out[:,0:13]
    combine_kernel<<<MTOT/256, blk>>>(pa, pc, Ab3, Cb3, out_main);
}

// round 17
// speedup vs baseline: 1.0244x; 1.0244x over previous
#include <cuda_runtime.h>
#include <cuda_fp16.h>
#include <math.h>
#include <stdint.h>

// Problem dims
#define BB 4096
#define TT 64
#define FF 256
#define HH 256
#define AA 12
#define MTOT (BB*TT)            // 262144 rows
#define G3  768

// Scratch (device globals; no cudaMalloc allowed)
__device__ __half g_xgh [(size_t)MTOT * G3];   // xg half; reused as t12 [M,512]
__device__ __half g_lath[(size_t)MTOT * HH];   // latent half
__device__ __half g_t1h [(size_t)MTOT * HH];   // features half
__device__ float  g_pa  [(size_t)2 * MTOT * 16];
__device__ float  g_pc  [(size_t)2 * MTOT];
__device__ uint32_t g_wt2h[16 * 7168];         // W_hh frag-major half2 slots
__device__ __half g_wihr[768 * 256];
__device__ __half g_w1c [512 * 256];
__device__ __half g_w2a [256 * 256];
__device__ __half g_w2c [256 * 256];
__device__ float  g_b1c [512];
__device__ float  g_w3f [4096];                // Aw3 tf32 B-fragments (head)

__device__ __forceinline__ float round_tf32(float x) {
    uint32_t r;
    asm("cvt.rna.tf32.f32 %0, %1;" : "=r"(r) : "f"(x));
    return __uint_as_float(r);
}
__device__ __forceinline__ uint32_t cvt_tf32_f(float x) {
    uint32_t r;
    asm("cvt.rna.tf32.f32 %0, %1;" : "=r"(r) : "f"(x));
    return r;
}

__device__ __forceinline__ uint32_t smem_u32(const void* p) {
    uint32_t a;
    asm("{ .reg .u64 t; cvta.to.shared.u64 t, %1; cvt.u32.u64 %0, t; }"
        : "=r"(a) : "l"(p));
    return a;
}

__device__ __forceinline__ void cp16_cg(void* dst, const void* src) {
    asm volatile("cp.async.cg.shared.global [%0], [%1], 16;"
                 :: "r"(smem_u32(dst)), "l"(src) : "memory");
}
__device__ __forceinline__ void l2_prefetch(const void* p) {
    asm volatile("prefetch.global.L2 [%0];" :: "l"(p));
}
#define CP_COMMIT()  asm volatile("cp.async.commit_group;" ::: "memory")
#define CP_WAIT1()   asm volatile("cp.async.wait_group 1;" ::: "memory")
#define CP_WAIT2()   asm volatile("cp.async.wait_group 2;" ::: "memory")
#define CP_WAITALL() asm volatile("cp.async.wait_all;" ::: "memory")

#define LDMX4(r0,r1,r2,r3,addr) \
    asm volatile("ldmatrix.sync.aligned.m8n8.x4.shared.b16 {%0,%1,%2,%3}, [%4];" \
                 : "=r"(r0),"=r"(r1),"=r"(r2),"=r"(r3) : "r"(addr))
#define LDMX2(r0,r1,addr) \
    asm volatile("ldmatrix.sync.aligned.m8n8.x2.shared.b16 {%0,%1}, [%2];" \
                 : "=r"(r0),"=r"(r1) : "r"(addr))

__device__ __forceinline__ void mma_f16(
    float& c0, float& c1, float& c2, float& c3,
    uint32_t a0, uint32_t a1, uint32_t a2, uint32_t a3,
    uint32_t b0, uint32_t b1)
{
    asm volatile(
        "mma.sync.aligned.m16n8k16.row.col.f32.f16.f16.f32 "
        "{%0,%1,%2,%3}, {%4,%5,%6,%7}, {%8,%9}, {%0,%1,%2,%3};"
        : "+f"(c0), "+f"(c1), "+f"(c2), "+f"(c3)
        : "r"(a0), "r"(a1), "r"(a2), "r"(a3), "r"(b0), "r"(b1));
}
__device__ __forceinline__ void mma_tf32(
    float& c0, float& c1, float& c2, float& c3,
    uint32_t a0, uint32_t a1, uint32_t a2, uint32_t a3,
    uint32_t b0, uint32_t b1)
{
    asm volatile(
        "mma.sync.aligned.m16n8k8.row.col.f32.tf32.tf32.f32 "
        "{%0,%1,%2,%3}, {%4,%5,%6,%7}, {%8,%9}, {%0,%1,%2,%3};"
        : "+f"(c0), "+f"(c1), "+f"(c2), "+f"(c3)
        : "r"(a0), "r"(a1), "r"(a2), "r"(a3), "r"(b0), "r"(b1));
}

__device__ __forceinline__ uint32_t pack_h2(float a, float b) {
    __half2 h = __floats2half2_rn(a, b);
    return *(uint32_t*)&h;
}

// ===========================================================================
// Prep: all weights -> half (+ W_hh fragment-major half2 slots + Aw3 frags)
// ===========================================================================
#define PREP_F4  114688
#define PREP_WHH (PREP_F4 + 98304)            // 212992
#define PREP_TOT (PREP_WHH + 4096)            // 217088 -> 848 blocks
__global__ void prep_all(
    const float4* __restrict__ Wih, const float4* __restrict__ Aw1,
    const float4* __restrict__ Cw1, const float4* __restrict__ Aw2,
    const float4* __restrict__ Cw2, const float* __restrict__ Ab1,
    const float* __restrict__ Cb1, const float*  __restrict__ W_hh,
    const float*  __restrict__ Aw3,
    uint2* __restrict__ wihr, uint2* __restrict__ w1c,
    uint2* __restrict__ w2a, uint2* __restrict__ w2c,
    float* __restrict__ b1c, uint32_t* __restrict__ Wt2h,
    float* __restrict__ w3f)
{
    int i = blockIdx.x * 256 + threadIdx.x;
    if (i < PREP_F4) {
        const float4* src;
        uint2* dst;
        if (i < 49152)      { src = Wih + i;            dst = wihr + i; }
        else if (i < 65536) { src = Aw1 + (i - 49152);  dst = w1c + (i - 49152); }
        else if (i < 81920) { src = Cw1 + (i - 65536);  dst = w1c + 16384 + (i - 65536); }
        else if (i < 98304) { src = Aw2 + (i - 81920);  dst = w2a + (i - 81920); }
        else                { src = Cw2 + (i - 98304);  dst = w2c + (i - 98304); }
        float4 v = *src;
        *dst = make_uint2(pack_h2(v.x, v.y), pack_h2(v.z, v.w));
        if (i < 256)       b1c[i] = Ab1[i];
        else if (i < 512)  b1c[i] = Cb1[i - 256];
    } else if (i < PREP_WHH) {
        int j2 = i - PREP_F4;              // 0..98303
        int kt  = j2 / 6144;
        int rem = j2 % 6144;
        int s   = rem / 24;                // slot = wn*32+lane
        int idx = rem % 24;
        int wn = s >> 5, lane = s & 31;
        int j12 = idx >> 1, b = idx & 1;
        int g = j12 >> 2, nt = j12 & 3;
        int col = g * 256 + wn * 32 + nt * 8 + (lane >> 2);
        int k0  = kt * 16 + 2 * (lane & 3) + 8 * b;
        Wt2h[kt * 7168 + s * 28 + idx] =
            pack_h2(W_hh[(size_t)col * 256 + k0], W_hh[(size_t)col * 256 + k0 + 1]);
    } else if (i < PREP_TOT) {
        int j3 = i - PREP_WHH;             // 0..4095
        int ksubg = j3 >> 7;
        int rest  = j3 & 127;
        int ntile = rest >> 6;
        int lane  = (rest >> 1) & 31;
        int r     = rest & 1;
        int kg = ksubg * 8 + (lane & 3) + 4 * r;
        int a  = ntile * 8 + (lane >> 2);
        w3f[j3] = (a < AA) ? round_tf32(Aw3[a * 256 + kg]) : 0.f;
    }
}

// features fp32 -> half
__global__ void feat_half(const float4* __restrict__ src, uint2* __restrict__ dst)
{
    size_t i = (size_t)blockIdx.x * 256 + threadIdx.x;
    float4 v = src[i];
    dst[i] = make_uint2(pack_h2(v.x, v.y), pack_h2(v.z, v.w));
}

// ===========================================================================
// fp16 mma GEMM: tile 128x128, BK=32 (2 x k16 steps), 3-stage cp.async,
// 2 CTAs/SM, ldmatrix fragments, per-CTA k-tile rotation.
// ===========================================================================
#define GBM 128
#define GBN 128
#define GBK 32
#define PH 40                                  // halves pitch (80B rows)
#define ASTG (GBM * PH)                        // 5120 halves per A/B stage
#define GEMM_SMEM (6 * ASTG * 2 + GBN * 4)     // 61440 + 512 = 61952 B

__device__ __forceinline__ void gemm16_mainloop(
    __half* smh, const __half* Ag, const __half* Wg,
    int K, int a_lm, int b_lm, float acc[4][4][4],
    int lrow, int lkq, int phase)
{
    const uint32_t sbase = smem_u32(smh);
    const int NK = K / GBK;                    // 8 for K=256
    auto stage_copy = [&](int kt) {
        int tl = kt + phase;
        if (tl >= NK) tl -= NK;
        __half* st = smh + (kt % 3) * 2 * ASTG;
        const __half* ap = Ag + tl * GBK;
        const __half* wp = Wg + tl * GBK;
        __half* dA = st + lrow * PH + lkq;
        __half* dB = st + ASTG + lrow * PH + lkq;
        cp16_cg(dA,     ap);
        cp16_cg(dA + 8, ap + 8);
        cp16_cg(dB,     wp);
        cp16_cg(dB + 8, wp + 8);
    };
    stage_copy(0); CP_COMMIT();
    stage_copy(1); CP_COMMIT();
    stage_copy(2); CP_COMMIT();
    for (int kt = 0; kt < NK; kt++) {
        if (kt < NK - 2)      { CP_WAIT2(); }
        else if (kt == NK - 2){ CP_WAIT1(); }
        else                  { CP_WAITALL(); }
        __syncthreads();
        const uint32_t bufA = sbase + ((kt % 3) * 2 * ASTG) * 2;
        const uint32_t bufB = bufA + ASTG * 2;
#pragma unroll
        for (int ks = 0; ks < 2; ks++) {
            const int k0 = ks * 16;
            uint32_t a[4][4];
#pragma unroll
            for (int mt = 0; mt < 4; mt++)
                LDMX4(a[mt][0], a[mt][1], a[mt][2], a[mt][3],
                      bufA + (a_lm + mt * 16 * PH + k0) * 2);
            uint32_t b[4][2];
#pragma unroll
            for (int nt = 0; nt < 4; nt++)
                LDMX2(b[nt][0], b[nt][1],
                      bufB + (b_lm + nt * 8 * PH + k0) * 2);
#pragma unroll
            for (int mt = 0; mt < 4; mt++)
#pragma unroll
                for (int nt = 0; nt < 4; nt++)
                    mma_f16(acc[mt][nt][0], acc[mt][nt][1],
                            acc[mt][nt][2], acc[mt][nt][3],
                            a[mt][0], a[mt][1], a[mt][2], a[mt][3],
                            b[nt][0], b[nt][1]);
        }
        __syncthreads();
        if (kt + 3 < NK) { stage_copy(kt + 3); CP_COMMIT(); }
    }
}

template<bool DO_TANH>
__global__ __launch_bounds__(256, 2) void gemm_h(
    const __half* __restrict__ A, const __half* __restrict__ W,
    const float* __restrict__ bias, __half* __restrict__ C,
    int N, int K, int lda)
{
    extern __shared__ __half smh[];
    float* sBias = (float*)(smh + 6 * ASTG);
    const int tid  = threadIdx.x;
    const int lane = tid & 31;
    const int wid  = tid >> 5;
    const int wm   = wid >> 2;
    const int wn   = wid & 3;
    const int    bn = blockIdx.x * GBN;
    const size_t bm = (size_t)blockIdx.y * GBM;
    if (tid < GBN) sBias[tid] = bias[bn + tid];
    const int lrow = tid >> 1;
    const int lkq  = (tid & 1) * 16;
    const __half* Ag = A + (bm + lrow) * lda + lkq;
    const __half* Wg = W + ((size_t)(bn + lrow)) * K + lkq;
    const int a_lm = (wm * 64 + (lane & 15)) * PH + ((lane >> 4) << 3);
    const int b_lm = (wn * 32 + (lane & 7)) * PH + (((lane >> 3) & 1) << 3);
    const int phase = blockIdx.y & ((K / GBK) - 1);

    float acc[4][4][4];
#pragma unroll
    for (int mt = 0; mt < 4; mt++)
#pragma unroll
        for (int nt = 0; nt < 4; nt++)
#pragma unroll
            for (int q = 0; q < 4; q++) acc[mt][nt][q] = 0.f;

    gemm16_mainloop(smh, Ag, Wg, K, a_lm, b_lm, acc, lrow, lkq, phase);

#pragma unroll
    for (int mt = 0; mt < 4; mt++) {
        const size_t row = bm + wm * 64 + mt * 16 + (lane >> 2);
        __half* c0p = C + row * N + bn + wn * 32;
        __half* c1p = c0p + (size_t)8 * N;
#pragma unroll
        for (int nt = 0; nt < 4; nt++) {
            const int cc = nt * 8 + (lane & 3) * 2;
            const float bx = sBias[wn * 32 + cc];
            const float by = sBias[wn * 32 + cc + 1];
            float v0 = acc[mt][nt][0] + bx, v1 = acc[mt][nt][1] + by;
            float v2 = acc[mt][nt][2] + bx, v3 = acc[mt][nt][3] + by;
            if (DO_TANH) {
                v0 = tanhf(v0); v1 = tanhf(v1);
                v2 = tanhf(v2); v3 = tanhf(v3);
            }
            *(uint32_t*)(c0p + cc) = pack_h2(v0, v1);
            *(uint32_t*)(c1p + cc) = pack_h2(v2, v3);
        }
    }
}

// ===========================================================================
// Layer-2 GEMM (fp16 mainloop) fused with heads -> partials.
// ===========================================================================
template<bool ACTOR>
__global__ __launch_bounds__(256, 2) void gemm_l2(
    const __half* __restrict__ A, const __half* __restrict__ W,
    const float* __restrict__ bias, const float* __restrict__ w3f,
    const float* __restrict__ Cw3,
    float* __restrict__ partial, int K, int lda)
{
    extern __shared__ __half smh[];
    float* sBias = (float*)(smh + 6 * ASTG);
    float* sred  = (float*)smh;             // reuse stage area post-mainloop
    const int tid  = threadIdx.x;
    const int lane = tid & 31;
    const int wid  = tid >> 5;
    const int wm   = wid >> 2;
    const int wn   = wid & 3;
    const int    bn = blockIdx.x * GBN;
    const size_t bm = (size_t)blockIdx.y * GBM;
    if (tid < GBN) sBias[tid] = bias[bn + tid];
    const int lrow = tid >> 1;
    const int lkq  = (tid & 1) * 16;
    const __half* Ag = A + (bm + lrow) * lda + lkq;
    const __half* Wg = W + ((size_t)(bn + lrow)) * K + lkq;
    const int a_lm = (wm * 64 + (lane & 15)) * PH + ((lane >> 4) << 3);
    const int b_lm = (wn * 32 + (lane & 7)) * PH + (((lane >> 3) & 1) << 3);
    const int phase = blockIdx.y & ((K / GBK) - 1);

    float acc[4][4][4];
#pragma unroll
    for (int mt = 0; mt < 4; mt++)
#pragma unroll
        for (int nt = 0; nt < 4; nt++)
#pragma unroll
            for (int q = 0; q < 4; q++) acc[mt][nt][q] = 0.f;

    gemm16_mainloop(smh, Ag, Wg, K, a_lm, b_lm, acc, lrow, lkq, phase);

#pragma unroll
    for (int mt = 0; mt < 4; mt++)
#pragma unroll
        for (int nt = 0; nt < 4; nt++) {
            const int cc = nt * 8 + (lane & 3) * 2;
            const float bx = sBias[wn * 32 + cc];
            const float by = sBias[wn * 32 + cc + 1];
            acc[mt][nt][0] = tanhf(acc[mt][nt][0] + bx);
            acc[mt][nt][1] = tanhf(acc[mt][nt][1] + by);
            acc[mt][nt][2] = tanhf(acc[mt][nt][2] + bx);
            acc[mt][nt][3] = tanhf(acc[mt][nt][3] + by);
        }

    const int j    = lane & 3;
    const int srcA = (lane & ~3) | (j >> 1);
    const int srcB = (lane & ~3) | (2 + (j >> 1));
    const bool odd = (lane & 1);

    if (ACTOR) {
        float hacc[4][2][4];
#pragma unroll
        for (int mt = 0; mt < 4; mt++)
#pragma unroll
            for (int n2 = 0; n2 < 2; n2++)
#pragma unroll
                for (int q = 0; q < 4; q++) hacc[mt][n2][q] = 0.f;

        const int ksgbase = (bn >> 3) + wn * 4;
#pragma unroll
        for (int ks = 0; ks < 4; ks++) {
            float2 bf0 = *(const float2*)(w3f + (((ksgbase + ks) * 2 + 0) * 32 + lane) * 2);
            float2 bf1 = *(const float2*)(w3f + (((ksgbase + ks) * 2 + 1) * 32 + lane) * 2);
            uint32_t b00 = __float_as_uint(bf0.x), b01 = __float_as_uint(bf0.y);
            uint32_t b10 = __float_as_uint(bf1.x), b11 = __float_as_uint(bf1.y);
#pragma unroll
            for (int mt = 0; mt < 4; mt++) {
                float c0 = acc[mt][ks][0], c1 = acc[mt][ks][1];
                float c2 = acc[mt][ks][2], c3 = acc[mt][ks][3];
                float t0 = __shfl_sync(0xffffffffu, c0, srcA);
                float t1 = __shfl_sync(0xffffffffu, c1, srcA);
                float t2 = __shfl_sync(0xffffffffu, c2, srcA);
                float t3 = __shfl_sync(0xffffffffu, c3, srcA);
                float u0 = __shfl_sync(0xffffffffu, c0, srcB);
                float u1 = __shfl_sync(0xffffffffu, c1, srcB);
                float u2 = __shfl_sync(0xffffffffu, c2, srcB);
                float u3 = __shfl_sync(0xffffffffu, c3, srcB);
                uint32_t a0 = cvt_tf32_f(odd ? t1 : t0);
                uint32_t a1 = cvt_tf32_f(odd ? t3 : t2);
                uint32_t a2 = cvt_tf32_f(odd ? u1 : u0);
                uint32_t a3 = cvt_tf32_f(odd ? u3 : u2);
                mma_tf32(hacc[mt][0][0], hacc[mt][0][1], hacc[mt][0][2], hacc[mt][0][3],
                         a0, a1, a2, a3, b00, b01);
                mma_tf32(hacc[mt][1][0], hacc[mt][1][1], hacc[mt][1][2], hacc[mt][1][3],
                         a0, a1, a2, a3, b10, b11);
            }
        }
        for (int rr = 0; rr < 4; rr++) {
            if (wn == rr) {
#pragma unroll
                for (int mt = 0; mt < 4; mt++)
#pragma unroll
                    for (int n2 = 0; n2 < 2; n2++)
#pragma unroll
                        for (int q = 0; q < 4; q++) {
                            int row = wm * 64 + mt * 16 + (lane >> 2) + 8 * (q >> 1);
                            int col = n2 * 8 + 2 * (lane & 3) + (q & 1);
                            if (rr == 0) sred[row * 17 + col] = hacc[mt][n2][q];
                            else         sred[row * 17 + col] += hacc[mt][n2][q];
                        }
            }
            __syncthreads();
        }
        const size_t pbase = (size_t)blockIdx.x * MTOT * 16 + bm * 16;
        for (int i = tid; i < 128 * 16; i += 256)
            partial[pbase + i] = sred[(i >> 4) * 17 + (i & 15)];
    } else {
        float2 cw[4];
#pragma unroll
        for (int nt = 0; nt < 4; nt++)
            cw[nt] = *(const float2*)(Cw3 + bn + wn * 32 + nt * 8 + 2 * (lane & 3));
        float rsum[4][2];
#pragma unroll
        for (int mt = 0; mt < 4; mt++) {
            float s0 = 0.f, s1 = 0.f;
#pragma unroll
            for (int nt = 0; nt < 4; nt++) {
                s0 = fmaf(acc[mt][nt][0], cw[nt].x, s0);
                s0 = fmaf(acc[mt][nt][1], cw[nt].y, s0);
                s1 = fmaf(acc[mt][nt][2], cw[nt].x, s1);
                s1 = fmaf(acc[mt][nt][3], cw[nt].y, s1);
            }
            s0 += __shfl_xor_sync(0xffffffffu, s0, 1);
            s0 += __shfl_xor_sync(0xffffffffu, s0, 2);
            s1 += __shfl_xor_sync(0xffffffffu, s1, 1);
            s1 += __shfl_xor_sync(0xffffffffu, s1, 2);
            rsum[mt][0] = s0; rsum[mt][1] = s1;
        }
        for (int rr = 0; rr < 4; rr++) {
            if (wn == rr && (lane & 3) == 0) {
#pragma unroll
                for (int mt = 0; mt < 4; mt++)
#pragma unroll
                    for (int qh = 0; qh < 2; qh++) {
                        int row = wm * 64 + mt * 16 + (lane >> 2) + 8 * qh;
                        if (rr == 0) sred[row] = rsum[mt][qh];
                        else         sred[row] += rsum[mt][qh];
                    }
            }
            __syncthreads();
        }
        const size_t pbase = (size_t)blockIdx.x * MTOT + bm;
        if (tid < 128) partial[pbase + tid] = sred[tid];
    }
}

// combine partials -> out[:,0:13]
__global__ __launch_bounds__(256) void combine_kernel(
    const float* __restrict__ pa, const float* __restrict__ pc,
    const float* __restrict__ Ab3, const float* __restrict__ Cb3,
    float* __restrict__ out)
{
    size_t m = (size_t)blockIdx.x * 256 + threadIdx.x;
    const float* p0 = pa + m * 16;
    const float* p1 = pa + (size_t)MTOT * 16 + m * 16;
    float* o = out + m * 13;
#pragma unroll
    for (int a = 0; a < 12; a++)
        o[a] = p0[a] + p1[a] + Ab3[a];
    o[12] = pc[m] + pc[MTOT + m] + Cb3[0];
}

// ===========================================================================
// GRU scan fp16 (unchanged from R15)
// ===========================================================================
#define RB2 32
#define HT_PH 264
#define WS_U32 7168
#define GRU_SMEM (3*WS_U32*4 + 32*HT_PH*2 + 32*64*4 + 768*4)   // 114176 B

__global__ __launch_bounds__(512, 1) void gru_mma(
    const __half* __restrict__ xgh, const float* __restrict__ h0,
    const uint32_t* __restrict__ Wt2h, const float* __restrict__ b_hh,
    const int* __restrict__ starts,
    __half* __restrict__ lath, float* __restrict__ h_out)
{
    extern __shared__ char smraw[];
    uint32_t* ws  = (uint32_t*)smraw;
    __half*   hth = (__half*)(ws + 3 * WS_U32);
    int*      sst = (int*)(hth + 32 * HT_PH);
    float*    sbh = (float*)(sst + 32 * 64);

    const int tid  = threadIdx.x;
    const int lane = tid & 31;
    const int w    = tid >> 5;
    const int wm   = w >> 3;
    const int wn   = w & 7;
    const int b0   = blockIdx.x * RB2;
    const int phase = blockIdx.x & 15;

    for (int i = tid; i < 32 * 64; i += 512)
        sst[i] = starts[(size_t)(b0 + (i >> 6)) * TT + (i & 63)];
    for (int i = tid; i < 768; i += 512) sbh[i] = b_hh[i];

    float2 hreg[2][4];
#pragma unroll
    for (int rh = 0; rh < 2; rh++) {
        const int row = wm * 16 + rh * 8 + (lane >> 2);
        const float m0 = starts[(size_t)(b0 + row) * TT] ? 0.f : 1.f;
#pragma unroll
        for (int nt = 0; nt < 4; nt++) {
            const int c = wn * 32 + nt * 8 + (lane & 3) * 2;
            float2 v = *(const float2*)(h0 + (size_t)(b0 + row) * 256 + c);
            v.x *= m0; v.y *= m0;
            hreg[rh][nt] = v;
            *(uint32_t*)(hth + row * HT_PH + c) = pack_h2(v.x, v.y);
        }
    }

    auto stageW = [&](int tile, int buf) {
        const float4* src = (const float4*)(Wt2h + (size_t)tile * WS_U32);
        float4* dst = (float4*)(ws + buf * WS_U32);
        cp16_cg(dst + tid,        src + tid);
        cp16_cg(dst + 512 + tid,  src + 512 + tid);
        cp16_cg(dst + 1024 + tid, src + 1024 + tid);
        if (tid < 256) cp16_cg(dst + 1536 + tid, src + 1536 + tid);
    };

    stageW(phase, 0); CP_COMMIT();
    stageW((phase + 1) & 15, 1); CP_COMMIT();

    const uint32_t ht_lm = smem_u32(hth)
        + ((wm * 16 + (lane & 15)) * HT_PH + ((lane >> 4) << 3)) * 2;
    const int bslot = (wn * 32 + lane) * 28;

    const int KS_TOTAL = TT * 16;
    int ks = 0;

    for (int t = 0; t < TT; t++) {
        float acc[12][4];
#pragma unroll
        for (int j = 0; j < 12; j++)
#pragma unroll
            for (int q = 0; q < 4; q++) acc[j][q] = 0.f;

        for (int kt = 0; kt < 16; kt++) {
            if (ks < KS_TOTAL - 1) { CP_WAIT1(); } else { CP_WAITALL(); }
            __syncthreads();

            if (ks + 2 < KS_TOTAL) {
                stageW((phase + ks + 2) & 15, (ks + 2) % 3);
                CP_COMMIT();
            }

            if (tid < 24) {
                int li = kt * 24 + tid;
                int r = li / 12, cl = li % 12;
                l2_prefetch((const char*)(xgh + ((size_t)(b0 + r) * TT + t) * G3)
                            + cl * 128);
            }

            const int tc = (phase + ks) & 15;
            const uint32_t* wb = ws + (ks % 3) * WS_U32 + bslot;
            uint32_t a0, a1, a2, a3;
            LDMX4(a0, a1, a2, a3, ht_lm + tc * 32);
            float4 bf[6];
#pragma unroll
            for (int u = 0; u < 6; u++)
                bf[u] = *(const float4*)(wb + u * 4);
            const uint32_t* bw = (const uint32_t*)bf;
#pragma unroll
            for (int j = 0; j < 12; j++)
                mma_f16(acc[j][0], acc[j][1], acc[j][2], acc[j][3],
                        a0, a1, a2, a3, bw[j * 2], bw[j * 2 + 1]);
            ks++;
        }
        __syncthreads();

#pragma unroll
        for (int rh = 0; rh < 2; rh++) {
            const int row  = wm * 16 + rh * 8 + (lane >> 2);
            const int grow = b0 + row;
            const size_t gbt = (size_t)grow * TT + t;
            const __half* xb = xgh + gbt * G3;
            __half* lb = lath + gbt * 256;
            float msk = 1.f;
            if (t < TT - 1) msk = sst[row * 64 + t + 1] ? 0.f : 1.f;
            const int q = rh * 2;
#pragma unroll
            for (int nt = 0; nt < 4; nt++) {
                const int c = wn * 32 + nt * 8 + (lane & 3) * 2;
                float2 xr = __half22float2(*(const __half2*)(xb + c));
                float2 xz = __half22float2(*(const __half2*)(xb + 256 + c));
                float2 xn = __half22float2(*(const __half2*)(xb + 512 + c));
                float hr0 = acc[nt][q]         + sbh[c];
                float hr1 = acc[nt][q + 1]     + sbh[c + 1];
                float hz0 = acc[4 + nt][q]     + sbh[256 + c];
                float hz1 = acc[4 + nt][q + 1] + sbh[256 + c + 1];
                float hn0 = acc[8 + nt][q]     + sbh[512 + c];
                float hn1 = acc[8 + nt][q + 1] + sbh[512 + c + 1];
                float r0 = 1.f / (1.f + __expf(-(xr.x + hr0)));
                float r1 = 1.f / (1.f + __expf(-(xr.y + hr1)));
                float z0 = 1.f / (1.f + __expf(-(xz.x + hz0)));
                float z1 = 1.f / (1.f + __expf(-(xz.y + hz1)));
                float n0 = tanhf(xn.x + r0 * hn0);
                float n1 = tanhf(xn.y + r1 * hn1);
                float v0 = (1.f - z0) * n0 + z0 * hreg[rh][nt].x;
                float v1 = (1.f - z1) * n1 + z1 * hreg[rh][nt].y;
                *(uint32_t*)(lb + c) = pack_h2(v0, v1);
                if (t == TT - 1) {
                    *(float2*)(h_out + (size_t)grow * 256 + c) = make_float2(v0, v1);
                } else {
                    float m0 = v0 * msk, m1 = v1 * msk;
                    hreg[rh][nt] = make_float2(m0, m1);
                    *(uint32_t*)(hth + row * HT_PH + c) = pack_h2(m0, m1);
                }
            }
        }
    }
}

__global__ void std_kernel(const float* __restrict__ log_std, float* __restrict__ out)
{
    int a = threadIdx.x;
    if (a < AA) {
        float v = log_std[a];
        v = fminf(fmaxf(v, -2.0f), -0.5f);
        out[a] = __expf(v);
    }
}

// ---------------------------------------------------------------------------
extern "C" void kernel_launch(void* const* d_in, const int* in_sizes, int n_in,
                              void* d_out, int out_size)
{
    const float* features = (const float*)d_in[0];
    const float* hidden   = (const float*)d_in[1];
    const float* W_ih     = (const float*)d_in[2];
    const float* W_hh     = (const float*)d_in[3];
    const float* b_ih     = (const float*)d_in[4];
    const float* b_hh     = (const float*)d_in[5];
    const float* Aw1      = (const float*)d_in[6];
    const float* Ab1      = (const float*)d_in[7];
    const float* Aw2      = (const float*)d_in[8];
    const float* Ab2      = (const float*)d_in[9];
    const float* Aw3      = (const float*)d_in[10];
    const float* Ab3      = (const float*)d_in[11];
    const float* Cw1      = (const float*)d_in[12];
    const float* Cb1      = (const float*)d_in[13];
    const float* Cw2      = (const float*)d_in[14];
    const float* Cb2      = (const float*)d_in[15];
    const float* Cw3      = (const float*)d_in[16];
    const float* Cb3      = (const float*)d_in[17];
    const float* log_std  = (const float*)d_in[18];
    const int*   starts   = (const int*)d_in[19];

    float* out      = (float*)d_out;
    float* out_main = out;
    float* out_std  = out + (size_t)MTOT * 13;
    float* out_h    = out + (size_t)MTOT * 13 + AA;

    __half *xgh, *lath, *t1h, *wihr, *w1c, *w2a, *w2c;
    float *pa, *pc, *b1c, *w3f;
    uint32_t *wt2h;
    cudaGetSymbolAddress((void**)&xgh,  g_xgh);
    cudaGetSymbolAddress((void**)&lath, g_lath);
    cudaGetSymbolAddress((void**)&t1h,  g_t1h);
    cudaGetSymbolAddress((void**)&pa,   g_pa);
    cudaGetSymbolAddress((void**)&pc,   g_pc);
    cudaGetSymbolAddress((void**)&wt2h, g_wt2h);
    cudaGetSymbolAddress((void**)&wihr, g_wihr);
    cudaGetSymbolAddress((void**)&w1c,  g_w1c);
    cudaGetSymbolAddress((void**)&w2a,  g_w2a);
    cudaGetSymbolAddress((void**)&w2c,  g_w2c);
    cudaGetSymbolAddress((void**)&b1c,  g_b1c);
    cudaGetSymbolAddress((void**)&w3f,  g_w3f);

    cudaFuncSetAttribute(gemm_h<false>,
                         cudaFuncAttributeMaxDynamicSharedMemorySize, GEMM_SMEM);
    cudaFuncSetAttribute(gemm_h<true>,
                         cudaFuncAttributeMaxDynamicSharedMemorySize, GEMM_SMEM);
    cudaFuncSetAttribute(gemm_l2<true>,
                         cudaFuncAttributeMaxDynamicSharedMemorySize, GEMM_SMEM);
    cudaFuncSetAttribute(gemm_l2<false>,
                         cudaFuncAttributeMaxDynamicSharedMemorySize, GEMM_SMEM);
    cudaFuncSetAttribute(gru_mma,
                         cudaFuncAttributeMaxDynamicSharedMemorySize, GRU_SMEM);

    dim3 blk(256);

    // 1) weight prep
    prep_all<<<PREP_TOT/256, blk>>>(
        (const float4*)W_ih, (const float4*)Aw1, (const float4*)Cw1,
        (const float4*)Aw2, (const float4*)Cw2, Ab1, Cb1, W_hh, Aw3,
        (uint2*)wihr, (uint2*)w1c, (uint2*)w2a, (uint2*)w2c,
        b1c, wt2h, w3f);
    // 2) features -> half
    feat_half<<<((size_t)MTOT*256)/1024, blk>>>(
        (const float4*)features, (uint2*)t1h);
    // 3) xg = features @ W_ih^T + b_ih (half out)
    gemm_h<false><<<dim3(G3/GBN, MTOT/GBM), blk, GEMM_SMEM>>>(
        t1h, wihr, b_ih, xgh, G3, FF, FF);
    // 4) GRU scan -> lat (half), h_last (fp32)     <-- profiled launch
    gru_mma<<<BB/RB2, dim3(512), GRU_SMEM>>>(
        xgh, hidden, wt2h, b_hh, starts, lath, out_h);
    // 5) fused actor+critic layer1 (reuses g_xgh as [M,512] half)
    gemm_h<true><<<dim3(512/GBN, MTOT/GBM), blk, GEMM_SMEM>>>(
        lath, w1c, b1c, xgh, 512, HH, HH);
    // 6,7) layer2 + fused heads -> partials
    gemm_l2<true><<<dim3(HH/GBN, MTOT/GBM), blk, GEMM_SMEM>>>(
        xgh,       w2a, Ab2, w3f, Cw3, pa, HH, 512);
    gemm_l2<false><<<dim3(HH/GBN, MTOT/GBM), blk, GEMM_SMEM>>>(
        xgh + 256, w2c, Cb2, w3f, Cw3, pc, HH, 512);
    // 8) combine partials + biases -> out[:,0:13]
    combine_kernel<<<MTOT/256, blk>>>(pa, pc, Ab3, Cb3, out_main);
    // 9) std
    std_kernel<<<1, 32>>>(log_std, out_std);
}